// round 3
// baseline (speedup 1.0000x reference)
#include <cuda_runtime.h>
#include <cstdint>

// Problem constants (fixed shapes per reference)
#define N_NODES 100000
#define F_IN    256
#define H_DIM   128
#define D_DIM   64

// ---------------- scratch (device globals; no allocation allowed) -------------
__device__ __align__(16) float g_dis [N_NODES];              // deg -> rsqrt(deg)
__device__ __align__(16) float g_h1  [N_NODES * H_DIM];      // x @ W1
__device__ __align__(16) float g_agg1[N_NODES * H_DIM];      // aggregated layer-1 pre-act
__device__ __align__(16) float g_h2  [N_NODES * H_DIM];      // relu(agg1 + b1)
__device__ __align__(16) float g_agg2[N_NODES * H_DIM];      // aggregated h2
__device__ __align__(16) float g_Wc  [H_DIM * 128];          // [Wmu | Wvar] row-major [128,128]
__device__ __align__(16) float g_bc  [128];                  // [bmu | bvar]

// ---------------- degree / normalization --------------------------------------
__global__ void deg_init_kernel() {
    int i = blockIdx.x * blockDim.x + threadIdx.x;
    if (i < N_NODES) g_dis[i] = 1.0f;          // self-loop contributes 1
}

__global__ void deg_count_kernel(const int* __restrict__ dst, int E) {
    int i = blockIdx.x * blockDim.x + threadIdx.x;
    if (i < E) atomicAdd(&g_dis[dst[i]], 1.0f);
}

__global__ void deg_rsqrt_kernel() {
    int i = blockIdx.x * blockDim.x + threadIdx.x;
    if (i < N_NODES) g_dis[i] = rsqrtf(g_dis[i]);
}

// ---------------- pack [Wmu|Wvar] and [bmu|bvar] -------------------------------
__global__ void pack_w_kernel(const float* __restrict__ Wmu, const float* __restrict__ Wvar,
                              const float* __restrict__ bmu, const float* __restrict__ bvar) {
    int i = blockIdx.x * blockDim.x + threadIdx.x;   // 0 .. 128*128-1
    if (i < H_DIM * 128) {
        int k = i >> 7, c = i & 127;
        g_Wc[i] = (c < D_DIM) ? Wmu[k * D_DIM + c] : Wvar[k * D_DIM + (c - D_DIM)];
    }
    if (i < 128) g_bc[i] = (i < D_DIM) ? bmu[i] : bvar[i - D_DIM];
}

// ---------------- SGEMM: C[M,128] = A[M,K] @ B[K,128] ---------------------------
// MODE 0: A = param (x), B = param (W1), writes g_h1
// MODE 1: A = g_agg2,    B = g_Wc, bias g_bc, split-writes mu/sigma into d_out
template <int MODE>
__global__ void __launch_bounds__(256)
sgemm_kernel(const float* __restrict__ Ap, const float* __restrict__ Bp,
             float* __restrict__ outMu, float* __restrict__ outSig,
             int M, int K) {
    __shared__ float As[8][128];
    __shared__ float Bs[8][128];

    const float* A = (MODE == 0) ? Ap : g_agg2;
    const float* B = (MODE == 0) ? Bp : g_Wc;

    int tid  = threadIdx.x;
    int row0 = blockIdx.x * 128;
    int tx   = tid & 15;      // column group (8 cols each)
    int ty   = tid >> 4;      // row group (8 rows each)

    float acc[8][8];
#pragma unroll
    for (int i = 0; i < 8; i++)
#pragma unroll
        for (int j = 0; j < 8; j++) acc[i][j] = 0.0f;

    for (int k0 = 0; k0 < K; k0 += 8) {
#pragma unroll
        for (int i = 0; i < 4; i++) {
            int idx = tid + i * 256;              // 0..1023
            int r = idx >> 3, kk = idx & 7;       // A tile: 128 rows x 8 k
            int gr = row0 + r;
            As[kk][r] = (gr < M) ? A[(size_t)gr * K + k0 + kk] : 0.0f;
            int kk2 = idx >> 7, c = idx & 127;    // B tile: 8 k x 128 cols
            Bs[kk2][c] = B[(size_t)(k0 + kk2) * 128 + c];
        }
        __syncthreads();
#pragma unroll
        for (int kk = 0; kk < 8; kk++) {
            float a[8], b[8];
#pragma unroll
            for (int i = 0; i < 8; i++) a[i] = As[kk][ty * 8 + i];
#pragma unroll
            for (int j = 0; j < 8; j++) b[j] = Bs[kk][tx * 8 + j];
#pragma unroll
            for (int i = 0; i < 8; i++)
#pragma unroll
                for (int j = 0; j < 8; j++)
                    acc[i][j] = fmaf(a[i], b[j], acc[i][j]);
        }
        __syncthreads();
    }

#pragma unroll
    for (int i = 0; i < 8; i++) {
        int gr = row0 + ty * 8 + i;
        if (gr >= M) continue;
#pragma unroll
        for (int j = 0; j < 8; j++) {
            int c = tx * 8 + j;
            float v = acc[i][j];
            if (MODE == 0) {
                g_h1[(size_t)gr * 128 + c] = v;
            } else {
                v += g_bc[c];
                if (c < D_DIM) outMu[(size_t)gr * D_DIM + c] = v;
                else           outSig[(size_t)gr * D_DIM + (c - D_DIM)] = v;
            }
        }
    }
}

// ---------------- self-loop init: agg1 = h1 * dis^2 -----------------------------
__global__ void selfloop_init_kernel() {
    int idx = blockIdx.x * blockDim.x + threadIdx.x;   // over N_NODES*32 float4s
    if (idx >= N_NODES * 32) return;
    int node = idx >> 5, c4 = idx & 31;
    float d = g_dis[node];
    float d2 = d * d;
    float4 v = ((const float4*)(g_h1 + (size_t)node * 128))[c4];
    v.x *= d2; v.y *= d2; v.z *= d2; v.w *= d2;
    ((float4*)(g_agg1 + (size_t)node * 128))[c4] = v;
}

// ---------------- edge scatter: agg[dst] += h[src] * dis[src]*dis[dst] ----------
// One warp per edge; each lane handles one float4 (32 lanes * 4 = 128 features).
template <int LAYER>   // 0: h1->agg1, 1: h2->agg2
__global__ void __launch_bounds__(256)
scatter_kernel(const int* __restrict__ src, const int* __restrict__ dst, int E) {
    int warp = (blockIdx.x * blockDim.x + threadIdx.x) >> 5;
    int lane = threadIdx.x & 31;
    if (warp >= E) return;
    int s = src[warp];
    int d = dst[warp];
    float nrm = g_dis[s] * g_dis[d];
    const float* h  = (LAYER == 0) ? g_h1 : g_h2;
    float* agg      = (LAYER == 0) ? g_agg1 : g_agg2;
    float4 v = ((const float4*)(h + (size_t)s * 128))[lane];
    v.x *= nrm; v.y *= nrm; v.z *= nrm; v.w *= nrm;
    float* out = agg + (size_t)d * 128 + lane * 4;
    asm volatile("red.global.add.v4.f32 [%0], {%1,%2,%3,%4};"
                 :: "l"(out), "f"(v.x), "f"(v.y), "f"(v.z), "f"(v.w)
                 : "memory");
}

// ---------------- h2 = relu(agg1 + b1); agg2 = h2 * dis^2 ------------------------
__global__ void relu_init_kernel(const float* __restrict__ b1) {
    int idx = blockIdx.x * blockDim.x + threadIdx.x;   // over N_NODES*32 float4s
    if (idx >= N_NODES * 32) return;
    int node = idx >> 5, c4 = idx & 31;
    float4 v = ((const float4*)(g_agg1 + (size_t)node * 128))[c4];
    float4 b = ((const float4*)b1)[c4];
    v.x = fmaxf(v.x + b.x, 0.0f);
    v.y = fmaxf(v.y + b.y, 0.0f);
    v.z = fmaxf(v.z + b.z, 0.0f);
    v.w = fmaxf(v.w + b.w, 0.0f);
    ((float4*)(g_h2 + (size_t)node * 128))[c4] = v;
    float d = g_dis[node];
    float d2 = d * d;
    v.x *= d2; v.y *= d2; v.z *= d2; v.w *= d2;
    ((float4*)(g_agg2 + (size_t)node * 128))[c4] = v;
}

// --------------------------------------------------------------------------------
extern "C" void kernel_launch(void* const* d_in, const int* in_sizes, int n_in,
                              void* d_out, int out_size) {
    const float* x    = (const float*)d_in[0];
    const int*   ei   = (const int*)d_in[1];     // edge_index: int32 (JAX x64 disabled)
    const float* W1   = (const float*)d_in[2];
    const float* b1   = (const float*)d_in[3];
    const float* Wmu  = (const float*)d_in[4];
    const float* bmu  = (const float*)d_in[5];
    const float* Wvar = (const float*)d_in[6];
    const float* bvar = (const float*)d_in[7];

    const int E = in_sizes[1] / 2;
    const int* src = ei;
    const int* dst = ei + E;

    float* outMu  = (float*)d_out;
    float* outSig = (float*)d_out + (size_t)N_NODES * D_DIM;

    // normalization coefficients
    deg_init_kernel <<<(N_NODES + 255) / 256, 256>>>();
    deg_count_kernel<<<(E + 255) / 256, 256>>>(dst, E);
    deg_rsqrt_kernel<<<(N_NODES + 255) / 256, 256>>>();
    pack_w_kernel   <<<(H_DIM * 128 + 255) / 256, 256>>>(Wmu, Wvar, bmu, bvar);

    // layer 1: h1 = x @ W1 ; agg1 = aggregate(h1)
    sgemm_kernel<0><<<(N_NODES + 127) / 128, 256>>>(x, W1, nullptr, nullptr, N_NODES, F_IN);
    selfloop_init_kernel<<<(N_NODES * 32 + 255) / 256, 256>>>();
    scatter_kernel<0><<<(E * 32 + 255) / 256, 256>>>(src, dst, E);

    // activation + layer 2 aggregation
    relu_init_kernel<<<(N_NODES * 32 + 255) / 256, 256>>>(b1);
    scatter_kernel<1><<<(E * 32 + 255) / 256, 256>>>(src, dst, E);

    // fused mu/sigma projection: [agg2] @ [Wmu|Wvar] + [bmu|bvar]
    sgemm_kernel<1><<<(N_NODES + 127) / 128, 256>>>(nullptr, nullptr, outMu, outSig,
                                                    N_NODES, H_DIM);
}

// round 4
// speedup vs baseline: 1.3817x; 1.3817x over previous
#include <cuda_runtime.h>
#include <cstdint>

// Problem constants (fixed shapes per reference)
#define N_NODES 100000
#define F_IN    256
#define H_DIM   128
#define D_DIM   64
#define MAX_E   1700000

// ---------------- scratch (device globals; no allocation allowed) -------------
__device__ __align__(16) float g_dis [N_NODES];              // deg -> rsqrt(deg)
__device__ __align__(16) float g_norm[MAX_E];                // per-edge dis[s]*dis[d]
__device__ __align__(16) float g_h1  [N_NODES * H_DIM];      // x @ W1
__device__ __align__(16) float g_agg1[N_NODES * H_DIM];      // aggregated layer-1 pre-act
__device__ __align__(16) float g_h2  [N_NODES * H_DIM];      // relu(agg1 + b1)
__device__ __align__(16) float g_agg2[N_NODES * H_DIM];      // aggregated h2
__device__ __align__(16) float g_Wc  [H_DIM * 128];          // [Wmu | Wvar] row-major [128,128]
__device__ __align__(16) float g_bc  [128];                  // [bmu | bvar]

// ---------------- degree / normalization --------------------------------------
__global__ void deg_init_kernel() {
    int i = blockIdx.x * blockDim.x + threadIdx.x;
    if (i < N_NODES) g_dis[i] = 1.0f;          // self-loop contributes 1
}

__global__ void deg_count_kernel(const int* __restrict__ dst, int E) {
    int i = blockIdx.x * blockDim.x + threadIdx.x;
    if (i < E) atomicAdd(&g_dis[dst[i]], 1.0f);
}

__global__ void deg_rsqrt_kernel() {
    int i = blockIdx.x * blockDim.x + threadIdx.x;
    if (i < N_NODES) g_dis[i] = rsqrtf(g_dis[i]);
}

__global__ void norm_kernel(const int* __restrict__ src, const int* __restrict__ dst, int E) {
    int i = blockIdx.x * blockDim.x + threadIdx.x;
    if (i < E) g_norm[i] = g_dis[src[i]] * g_dis[dst[i]];
}

// ---------------- pack [Wmu|Wvar] and [bmu|bvar] -------------------------------
__global__ void pack_w_kernel(const float* __restrict__ Wmu, const float* __restrict__ Wvar,
                              const float* __restrict__ bmu, const float* __restrict__ bvar) {
    int i = blockIdx.x * blockDim.x + threadIdx.x;   // 0 .. 128*128-1
    if (i < H_DIM * 128) {
        int k = i >> 7, c = i & 127;
        g_Wc[i] = (c < D_DIM) ? Wmu[k * D_DIM + c] : Wvar[k * D_DIM + (c - D_DIM)];
    }
    if (i < 128) g_bc[i] = (i < D_DIM) ? bmu[i] : bvar[i - D_DIM];
}

// ---------------- SGEMM: C[M,128] = A[M,K] @ B[K,128] ---------------------------
// BM=128, BN=128, BK=16, 256 threads, 8x8 micro-tile, double-buffered smem.
// MODE 0: A = x,  B = W1; epilogue writes g_h1 AND g_agg1 = h1 * dis^2 (fused self-loop)
// MODE 1: A = g_agg2, B = g_Wc; epilogue adds g_bc, split-writes mu/sigma to d_out
template <int MODE>
__global__ void __launch_bounds__(256)
sgemm_kernel(const float* __restrict__ Ap, const float* __restrict__ Bp,
             float* __restrict__ outMu, float* __restrict__ outSig,
             int M, int K) {
    __shared__ float As[2][16][132];   // [buf][k][m] padded
    __shared__ float Bs[2][16][128];   // [buf][k][n]

    const float* A = (MODE == 0) ? Ap : g_agg2;
    const float* B = (MODE == 0) ? Bp : g_Wc;

    const int tid  = threadIdx.x;
    const int row0 = blockIdx.x * 128;
    const int tx   = tid & 15;        // column group (8 cols)
    const int ty   = tid >> 4;        // row group (8 rows)

    float acc[8][8];
#pragma unroll
    for (int i = 0; i < 8; i++)
#pragma unroll
        for (int j = 0; j < 8; j++) acc[i][j] = 0.0f;

    // tile loader: A tile 128x16 (transposed into As), B tile 16x128
    auto load_tile = [&](int k0, int buf) {
#pragma unroll
        for (int i = 0; i < 2; i++) {
            int lin = tid + i * 256;                 // 0..511
            // A: r = lin>>2 (0..127), q = lin&3 -> float4 at k0 + q*4
            int r = lin >> 2, q = (lin & 3) * 4;
            int gr = row0 + r;
            float4 va = make_float4(0.f, 0.f, 0.f, 0.f);
            if (gr < M) va = *(const float4*)&A[(size_t)gr * K + k0 + q];
            As[buf][q + 0][r] = va.x;
            As[buf][q + 1][r] = va.y;
            As[buf][q + 2][r] = va.z;
            As[buf][q + 3][r] = va.w;
            // B: k = lin>>5 (0..15), n = (lin&31)*4
            int bk = lin >> 5, bn = (lin & 31) * 4;
            *(float4*)&Bs[buf][bk][bn] = *(const float4*)&B[(size_t)(k0 + bk) * 128 + bn];
        }
    };

    const int steps = K / 16;
    load_tile(0, 0);
    __syncthreads();

    for (int s = 0; s < steps; s++) {
        if (s + 1 < steps) load_tile((s + 1) * 16, (s + 1) & 1);
        const int cb = s & 1;
#pragma unroll
        for (int kk = 0; kk < 16; kk++) {
            float4 a0 = *(const float4*)&As[cb][kk][ty * 8];
            float4 a1 = *(const float4*)&As[cb][kk][ty * 8 + 4];
            float4 b0 = *(const float4*)&Bs[cb][kk][tx * 8];
            float4 b1 = *(const float4*)&Bs[cb][kk][tx * 8 + 4];
            float a[8] = {a0.x, a0.y, a0.z, a0.w, a1.x, a1.y, a1.z, a1.w};
            float b[8] = {b0.x, b0.y, b0.z, b0.w, b1.x, b1.y, b1.z, b1.w};
#pragma unroll
            for (int i = 0; i < 8; i++)
#pragma unroll
                for (int j = 0; j < 8; j++)
                    acc[i][j] = fmaf(a[i], b[j], acc[i][j]);
        }
        __syncthreads();
    }

    if (MODE == 1) {
        float bc0[8];
#pragma unroll
        for (int j = 0; j < 8; j++) bc0[j] = g_bc[tx * 8 + j];
#pragma unroll
        for (int i = 0; i < 8; i++) {
            int gr = row0 + ty * 8 + i;
            if (gr >= M) continue;
            float4 v0 = make_float4(acc[i][0] + bc0[0], acc[i][1] + bc0[1],
                                    acc[i][2] + bc0[2], acc[i][3] + bc0[3]);
            float4 v1 = make_float4(acc[i][4] + bc0[4], acc[i][5] + bc0[5],
                                    acc[i][6] + bc0[6], acc[i][7] + bc0[7]);
            float* base = (tx < 8) ? (outMu + (size_t)gr * D_DIM + tx * 8)
                                   : (outSig + (size_t)gr * D_DIM + (tx - 8) * 8);
            *(float4*)&base[0] = v0;
            *(float4*)&base[4] = v1;
        }
    } else {
#pragma unroll
        for (int i = 0; i < 8; i++) {
            int gr = row0 + ty * 8 + i;
            if (gr >= M) continue;
            float d = g_dis[gr];
            float d2 = d * d;
            float4 v0 = make_float4(acc[i][0], acc[i][1], acc[i][2], acc[i][3]);
            float4 v1 = make_float4(acc[i][4], acc[i][5], acc[i][6], acc[i][7]);
            *(float4*)&g_h1[(size_t)gr * 128 + tx * 8]     = v0;
            *(float4*)&g_h1[(size_t)gr * 128 + tx * 8 + 4] = v1;
            float4 w0 = make_float4(v0.x * d2, v0.y * d2, v0.z * d2, v0.w * d2);
            float4 w1 = make_float4(v1.x * d2, v1.y * d2, v1.z * d2, v1.w * d2);
            *(float4*)&g_agg1[(size_t)gr * 128 + tx * 8]     = w0;
            *(float4*)&g_agg1[(size_t)gr * 128 + tx * 8 + 4] = w1;
        }
    }
}

// ---------------- edge scatter: agg[dst] += h[src] * norm[e] --------------------
// 4 edges per warp: lanes 0-3 load src, 4-7 load dst (coalesced), norm coalesced;
// distributed via shfl; 4 independent 16B gathers in flight per lane (MLP=4).
template <int LAYER>   // 0: h1->agg1, 1: h2->agg2
__global__ void __launch_bounds__(256)
scatter_kernel(const int* __restrict__ src, const int* __restrict__ dst, int E) {
    int warp = (blockIdx.x * blockDim.x + threadIdx.x) >> 5;
    int lane = threadIdx.x & 31;
    int e0 = warp * 4;
    if (e0 >= E) return;

    int   iv = 0;
    float nf = 0.0f;
    if (lane < 4) {
        int e = min(e0 + lane, E - 1);
        iv = src[e];
        nf = g_norm[e];
    } else if (lane < 8) {
        int e = min(e0 + lane - 4, E - 1);
        iv = dst[e];
    }

    const float* h = (LAYER == 0) ? g_h1 : g_h2;
    float* agg     = (LAYER == 0) ? g_agg1 : g_agg2;

    int   ss[4], dd[4];
    float nn[4];
#pragma unroll
    for (int j = 0; j < 4; j++) {
        ss[j] = __shfl_sync(0xffffffffu, iv, j);
        dd[j] = __shfl_sync(0xffffffffu, iv, 4 + j);
        nn[j] = __shfl_sync(0xffffffffu, nf, j);
    }

    float4 v[4];
#pragma unroll
    for (int j = 0; j < 4; j++)
        v[j] = ((const float4*)(h + (size_t)ss[j] * 128))[lane];

#pragma unroll
    for (int j = 0; j < 4; j++) {
        if (e0 + j < E) {
            float n = nn[j];
            float* out = agg + (size_t)dd[j] * 128 + lane * 4;
            asm volatile("red.global.add.v4.f32 [%0], {%1,%2,%3,%4};"
                         :: "l"(out), "f"(v[j].x * n), "f"(v[j].y * n),
                            "f"(v[j].z * n), "f"(v[j].w * n)
                         : "memory");
        }
    }
}

// ---------------- h2 = relu(agg1 + b1); agg2 = h2 * dis^2 ------------------------
__global__ void relu_init_kernel(const float* __restrict__ b1) {
    int idx = blockIdx.x * blockDim.x + threadIdx.x;   // over N_NODES*32 float4s
    if (idx >= N_NODES * 32) return;
    int node = idx >> 5, c4 = idx & 31;
    float4 v = ((const float4*)(g_agg1 + (size_t)node * 128))[c4];
    float4 b = ((const float4*)b1)[c4];
    v.x = fmaxf(v.x + b.x, 0.0f);
    v.y = fmaxf(v.y + b.y, 0.0f);
    v.z = fmaxf(v.z + b.z, 0.0f);
    v.w = fmaxf(v.w + b.w, 0.0f);
    ((float4*)(g_h2 + (size_t)node * 128))[c4] = v;
    float d = g_dis[node];
    float d2 = d * d;
    v.x *= d2; v.y *= d2; v.z *= d2; v.w *= d2;
    ((float4*)(g_agg2 + (size_t)node * 128))[c4] = v;
}

// --------------------------------------------------------------------------------
extern "C" void kernel_launch(void* const* d_in, const int* in_sizes, int n_in,
                              void* d_out, int out_size) {
    const float* x    = (const float*)d_in[0];
    const int*   ei   = (const int*)d_in[1];     // edge_index: int32
    const float* W1   = (const float*)d_in[2];
    const float* b1   = (const float*)d_in[3];
    const float* Wmu  = (const float*)d_in[4];
    const float* bmu  = (const float*)d_in[5];
    const float* Wvar = (const float*)d_in[6];
    const float* bvar = (const float*)d_in[7];

    const int E = in_sizes[1] / 2;
    const int* src = ei;
    const int* dst = ei + E;

    float* outMu  = (float*)d_out;
    float* outSig = (float*)d_out + (size_t)N_NODES * D_DIM;

    const int scatterWarps  = (E + 3) / 4;
    const int scatterBlocks = (scatterWarps * 32 + 255) / 256;

    // 1-3: degree / normalization
    deg_init_kernel <<<(N_NODES + 255) / 256, 256>>>();
    deg_count_kernel<<<(E + 255) / 256, 256>>>(dst, E);
    deg_rsqrt_kernel<<<(N_NODES + 255) / 256, 256>>>();

    // 4: layer-1 GEMM with fused self-loop init (h1, agg1)
    sgemm_kernel<0><<<(N_NODES + 127) / 128, 256>>>(x, W1, nullptr, nullptr, N_NODES, F_IN);

    // 5: per-edge norm precompute
    norm_kernel<<<(E + 255) / 256, 256>>>(src, dst, E);

    // 6: layer-1 edge scatter
    scatter_kernel<0><<<scatterBlocks, 256>>>(src, dst, E);

    // 7: relu + layer-2 self-loop init (h2, agg2)
    relu_init_kernel<<<(N_NODES * 32 + 255) / 256, 256>>>(b1);

    // 8: layer-2 edge scatter
    scatter_kernel<1><<<scatterBlocks, 256>>>(src, dst, E);

    // 9: pack fused projection weights
    pack_w_kernel<<<(H_DIM * 128 + 255) / 256, 256>>>(Wmu, Wvar, bmu, bvar);

    // 10: fused mu/sigma projection into d_out
    sgemm_kernel<1><<<(N_NODES + 127) / 128, 256>>>(nullptr, nullptr, outMu, outSig,
                                                    N_NODES, H_DIM);
}